// round 17
// baseline (speedup 1.0000x reference)
#include <cuda_runtime.h>

#define B_   256
#define R_   1152
#define C_   10
#define IC_  8
#define OC_  16
#define RT_  16
#define CHUNKS_ (R_/RT_)   /* 72 */
#define NG_   (B_*C_*OC_)  /* 40960 */

// Scratch (static device memory — no allocations).
__device__ __align__(16) float g_Vsum[NG_];             // running sum of v_j
__device__ __align__(16) float g_scratch[CHUNKS_*NG_];  // per-r-chunk partial s

// ---- packed fp32x2 helpers (Blackwell FFMA2 — only reachable via PTX) ------
typedef unsigned long long u64t;
__device__ __forceinline__ u64t fma2(u64t a, u64t b, u64t c) {
    u64t d;
    asm("fma.rn.f32x2 %0, %1, %2, %3;" : "=l"(d) : "l"(a), "l"(b), "l"(c));
    return d;
}
__device__ __forceinline__ u64t mul2(u64t a, u64t b) {
    u64t d;
    asm("mul.rn.f32x2 %0, %1, %2;" : "=l"(d) : "l"(a), "l"(b));
    return d;
}
__device__ __forceinline__ u64t bcast2(float x) {
    u64t d; unsigned int u = __float_as_uint(x);
    asm("mov.b64 %0, {%1, %1};" : "=l"(d) : "r"(u));
    return d;
}
__device__ __forceinline__ float2 unpack2(u64t v) {
    unsigned int lo, hi;
    asm("mov.b64 {%0, %1}, %2;" : "=r"(lo), "=r"(hi) : "l"(v));
    return make_float2(__uint_as_float(lo), __uint_as_float(hi));
}

// Shared layout: W tile [5120 float4] (80KB) then x tile [128][33 float4]
// (x rows padded 32->33 float4 so the 16 b-lanes land in distinct bank
// quarters: 528 B mod 128 = 16).
#define W_F4_    (RT_*C_*IC_*4)          /* 5120 float4 = 80 KB */
#define XPAD_    33
#define X_F4_    (128*XPAD_)             /* 4224 float4 = 66 KB */
#define SMEM_BYTES_ ((W_F4_ + X_F4_)*16) /* 149504 B */

__device__ __forceinline__ void load_w_tile(float4* Ws, const float* w,
                                            int chunk, int tid) {
    const float4* wsrc = reinterpret_cast<const float4*>(w)
                       + (size_t)chunk * W_F4_;
    #pragma unroll
    for (int k = 0; k < W_F4_/256; ++k) Ws[k*256 + tid] = wsrc[k*256 + tid];
}

// Stage x[b_base .. b_base+128) x [r0 .. r0+16) x [0..8) into padded smem.
// Global: 32 consecutive float4 per b (coalesced); smem rows padded to 33.
__device__ __forceinline__ void load_x_tile(float4* Xs, const float* x,
                                            int b_base, int r0, int tid) {
    const float4* gx = reinterpret_cast<const float4*>(x)
                     + (size_t)b_base * (R_*2) + r0*2;
    #pragma unroll
    for (int k = 0; k < 4096/256; ++k) {           // 16 iters
        int f = k*256 + tid;
        int bl  = f >> 5;
        int off = f & 31;
        Xs[bl*XPAD_ + off] = gx[(size_t)bl*(R_*2) + off];
    }
}

// ---------------------------------------------------------------------------
// First routing pass (uniform coupling 0.1): nb=2, osplit=4, packed f32x2.
// Grid (CHUNKS_, 2), block 256. Thread -> (batch pair, o-quarter).
// x read from staged smem tile.
// ---------------------------------------------------------------------------
__global__ __launch_bounds__(256, 1)
void pass_first(const float* __restrict__ x, const float* __restrict__ w) {
    extern __shared__ __align__(16) float4 Sm[];
    float4* Ws = Sm;
    float4* Xs = Sm + W_F4_;
    const int tid   = threadIdx.x;
    const int chunk = blockIdx.x;
    const int r0    = chunk * RT_;
    const int oq    = tid & 3;
    const int bl0   = (tid >> 2) * 2;              // local batch pair
    const int b0    = blockIdx.y * 128 + bl0;

    load_w_tile(Ws, w, chunk, tid);
    load_x_tile(Xs, x, blockIdx.y * 128, r0, tid);
    __syncthreads();

    u64t s0[C_][2], s1[C_][2];
    #pragma unroll
    for (int c = 0; c < C_; ++c) {
        s0[c][0] = 0ull; s0[c][1] = 0ull;
        s1[c][0] = 0ull; s1[c][1] = 0ull;
    }

    const float4* xs0 = Xs + bl0 * XPAD_;
    const float4* xs1 = xs0 + XPAD_;

    #pragma unroll 1
    for (int r = 0; r < RT_; ++r) {
        float4 xa = xs0[r*2];
        float4 xb = xs0[r*2 + 1];
        float4 ya = xs1[r*2];
        float4 yb = xs1[r*2 + 1];
        u64t x2[8], y2[8];
        x2[0]=bcast2(xa.x); x2[1]=bcast2(xa.y); x2[2]=bcast2(xa.z); x2[3]=bcast2(xa.w);
        x2[4]=bcast2(xb.x); x2[5]=bcast2(xb.y); x2[6]=bcast2(xb.z); x2[7]=bcast2(xb.w);
        y2[0]=bcast2(ya.x); y2[1]=bcast2(ya.y); y2[2]=bcast2(ya.z); y2[3]=bcast2(ya.w);
        y2[4]=bcast2(yb.x); y2[5]=bcast2(yb.y); y2[6]=bcast2(yb.z); y2[7]=bcast2(yb.w);

        const ulonglong2* wr2 =
            reinterpret_cast<const ulonglong2*>(Ws) + (size_t)r * (C_*IC_*4) + oq;
        #pragma unroll
        for (int c = 0; c < C_; ++c) {
            #pragma unroll
            for (int i = 0; i < IC_; ++i) {
                ulonglong2 q = wr2[(c*IC_ + i)*4];        // 16B smem broadcast
                s0[c][0] = fma2(x2[i], q.x, s0[c][0]);
                s0[c][1] = fma2(x2[i], q.y, s0[c][1]);
                s1[c][0] = fma2(y2[i], q.x, s1[c][0]);
                s1[c][1] = fma2(y2[i], q.y, s1[c][1]);
            }
        }
    }

    const u64t tenth = bcast2(0.1f);
    u64t* d0 = reinterpret_cast<u64t*>(g_scratch + ((size_t)chunk*B_ +  b0     )*(C_*OC_) + oq*4);
    u64t* d1 = reinterpret_cast<u64t*>(g_scratch + ((size_t)chunk*B_ + (b0 + 1))*(C_*OC_) + oq*4);
    #pragma unroll
    for (int c = 0; c < C_; ++c) {
        d0[c*8]     = mul2(s0[c][0], tenth);
        d0[c*8 + 1] = mul2(s0[c][1], tenth);
        d1[c*8]     = mul2(s1[c][0], tenth);
        d1[c*8 + 1] = mul2(s1[c][1], tenth);
    }
}

// ---------------------------------------------------------------------------
// Routing iteration pass: nb=1, osplit=2, f32x2, Vsum in regs, x from smem.
// Grid (CHUNKS_, 2), block 256. Thread -> (b = by*128 + tid>>1, oh = tid&1).
// ---------------------------------------------------------------------------
__global__ __launch_bounds__(256, 1)
void pass_iter(const float* __restrict__ x, const float* __restrict__ w) {
    extern __shared__ __align__(16) float4 Sm[];
    float4* Ws = Sm;
    float4* Xs = Sm + W_F4_;
    const int tid   = threadIdx.x;
    const int chunk = blockIdx.x;
    const int r0    = chunk * RT_;
    const int oh    = tid & 1;
    const int bl    = tid >> 1;                   // local batch 0..127
    const int b     = blockIdx.y * 128 + bl;

    load_w_tile(Ws, w, chunk, tid);
    load_x_tile(Xs, x, blockIdx.y * 128, r0, tid);

    // Hoist Vsum for this (b, o-half): loaded once per kernel.
    const ulonglong2* vsp =
        reinterpret_cast<const ulonglong2*>(g_Vsum + b * (C_*OC_) + oh * 8);
    ulonglong2 vsA[C_], vsB[C_];
    #pragma unroll
    for (int c = 0; c < C_; ++c) { vsA[c] = vsp[c*4]; vsB[c] = vsp[c*4 + 1]; }

    __syncthreads();

    u64t s2[C_][4];
    #pragma unroll
    for (int c = 0; c < C_; ++c)
        #pragma unroll
        for (int j = 0; j < 4; ++j) s2[c][j] = 0ull;

    const float4* xs = Xs + bl * XPAD_;

    #pragma unroll 1
    for (int r = 0; r < RT_; ++r) {
        float4 xa = xs[r*2];
        float4 xb = xs[r*2 + 1];
        u64t x2[8];
        x2[0]=bcast2(xa.x); x2[1]=bcast2(xa.y); x2[2]=bcast2(xa.z); x2[3]=bcast2(xa.w);
        x2[4]=bcast2(xb.x); x2[5]=bcast2(xb.y); x2[6]=bcast2(xb.z); x2[7]=bcast2(xb.w);

        const ulonglong2* wr2 =
            reinterpret_cast<const ulonglong2*>(Ws) + (size_t)r * (C_*IC_*4) + oh*2;

        u64t u2[C_][4];
        float t[C_];
        #pragma unroll
        for (int c = 0; c < C_; ++c) {
            u64t a0 = 0ull, a1 = 0ull, a2 = 0ull, a3 = 0ull;
            #pragma unroll
            for (int i = 0; i < IC_; ++i) {
                ulonglong2 pA = wr2[(c*IC_ + i)*4];
                ulonglong2 pB = wr2[(c*IC_ + i)*4 + 1];
                a0 = fma2(x2[i], pA.x, a0);
                a1 = fma2(x2[i], pA.y, a1);
                a2 = fma2(x2[i], pB.x, a2);
                a3 = fma2(x2[i], pB.y, a3);
            }
            u2[c][0]=a0; u2[c][1]=a1; u2[c][2]=a2; u2[c][3]=a3;
            // t partial from register-resident Vsum (no memory ops)
            u64t t2 = mul2(a0, vsA[c].x);
            t2 = fma2(a1, vsA[c].y, t2);
            t2 = fma2(a2, vsB[c].x, t2);
            t2 = fma2(a3, vsB[c].y, t2);
            float2 tp = unpack2(t2);
            float ta = tp.x + tp.y;
            // partner-lane completion INSIDE the loop: overlaps next c's FMAs
            t[c] = ta + __shfl_xor_sync(0xffffffffu, ta, 1);
        }

        // softmax over c (tree max, depth 4)
        float m = fmaxf(fmaxf(fmaxf(t[0],t[1]), fmaxf(t[2],t[3])),
                        fmaxf(fmaxf(t[4],t[5]), fmaxf(t[6],t[7])));
        m = fmaxf(m, fmaxf(t[8],t[9]));
        float z = 0.0f;
        #pragma unroll
        for (int c = 0; c < C_; ++c) { t[c] = __expf(t[c] - m); z += t[c]; }
        float inv = __fdividef(1.0f, z);

        #pragma unroll
        for (int c = 0; c < C_; ++c) {
            u64t cc2 = bcast2(t[c] * inv);
            s2[c][0] = fma2(cc2, u2[c][0], s2[c][0]);
            s2[c][1] = fma2(cc2, u2[c][1], s2[c][1]);
            s2[c][2] = fma2(cc2, u2[c][2], s2[c][2]);
            s2[c][3] = fma2(cc2, u2[c][3], s2[c][3]);
        }
    }

    u64t* dst = reinterpret_cast<u64t*>(
        g_scratch + ((size_t)chunk*B_ + b)*(C_*OC_) + oh*8);
    #pragma unroll
    for (int c = 0; c < C_; ++c) {
        dst[c*8]     = s2[c][0];
        dst[c*8 + 1] = s2[c][1];
        dst[c*8 + 2] = s2[c][2];
        dst[c*8 + 3] = s2[c][3];
    }
}

// ---------------------------------------------------------------------------
// Reduce 72 partials, squash, update Vsum / emit output.
// Block 768 = 32 g-float4 x 24 k-slices (3 loads each -> short serial chains),
// smem combine, 4-lane shfl squash on the first 32 threads. Grid 320.
// ---------------------------------------------------------------------------
template<bool FIRSTV, bool LAST>
__global__ __launch_bounds__(768, 1)
void squash_kernel(float* __restrict__ out) {
    const int tid = threadIdx.x;
    const int ks  = tid >> 5;          // 0..23
    const int gl  = tid & 31;          // 0..31
    const int g4  = blockIdx.x * 32 + gl;   // float4 index into [NG_/4]

    const float4* src = reinterpret_cast<const float4*>(g_scratch);
    float4 a = make_float4(0.f, 0.f, 0.f, 0.f);
    #pragma unroll
    for (int k = 0; k < CHUNKS_/24; ++k) {
        float4 tv = src[(size_t)(ks * (CHUNKS_/24) + k) * (NG_/4) + g4];
        a.x += tv.x; a.y += tv.y; a.z += tv.z; a.w += tv.w;
    }

    __shared__ float4 red[24][32];
    red[ks][gl] = a;
    __syncthreads();

    if (tid < 32) {
        float4 s = red[0][tid];
        #pragma unroll
        for (int j = 1; j < 24; ++j) {
            float4 t = red[j][tid];
            s.x += t.x; s.y += t.y; s.z += t.z; s.w += t.w;
        }
        float sq = s.x*s.x + s.y*s.y + s.z*s.z + s.w*s.w;
        sq += __shfl_xor_sync(0xffffffffu, sq, 1);      // 4 float4 lanes = one
        sq += __shfl_xor_sync(0xffffffffu, sq, 2);      // (b,c) 16-vector
        float n = sqrtf(sq);
        float sc = (sq / (1.0f + sq)) / (n + 1e-8f);
        float4 v = make_float4(s.x*sc, s.y*sc, s.z*sc, s.w*sc);
        int g = blockIdx.x * 32 + tid;
        if (LAST) {
            reinterpret_cast<float4*>(out)[g] = v;
        } else if (FIRSTV) {
            reinterpret_cast<float4*>(g_Vsum)[g] = v;
        } else {
            float4 o = reinterpret_cast<float4*>(g_Vsum)[g];
            o.x += v.x; o.y += v.y; o.z += v.z; o.w += v.w;
            reinterpret_cast<float4*>(g_Vsum)[g] = o;
        }
    }
}

extern "C" void kernel_launch(void* const* d_in, const int* in_sizes, int n_in,
                              void* d_out, int out_size) {
    const float* x = (const float*)d_in[0];
    const float* w = (const float*)d_in[1];
    float* out = (float*)d_out;

    cudaFuncSetAttribute(pass_first, cudaFuncAttributeMaxDynamicSharedMemorySize, SMEM_BYTES_);
    cudaFuncSetAttribute(pass_iter,  cudaFuncAttributeMaxDynamicSharedMemorySize, SMEM_BYTES_);

    dim3 grid(CHUNKS_, 2);   // 144 CTAs, 1 per SM

    pass_first<<<grid, 256, SMEM_BYTES_>>>(x, w);    // iter 1 (uniform coupling)
    squash_kernel<true,  false><<<320, 768>>>(out);  // v1, Vsum = v1
    pass_iter<<<grid, 256, SMEM_BYTES_>>>(x, w);     // iter 2
    squash_kernel<false, false><<<320, 768>>>(out);  // v2, Vsum = v1+v2
    pass_iter<<<grid, 256, SMEM_BYTES_>>>(x, w);     // iter 3
    squash_kernel<false, true ><<<320, 768>>>(out);  // v3 -> output
}